// round 4
// baseline (speedup 1.0000x reference)
#include <cuda_runtime.h>
#include <cuda_bf16.h>
#include <math.h>
#include <stdint.h>

// Problem constants
#define B_   4
#define S_   2048
#define HID_ 2048
#define NH_  16
#define HD_  128
#define CH_  16
#define LCH_ 128
#define M1_  (B_*S_)   // 8192

// GEMM tiling (warp-level mma.sync)
#define BM_ 128
#define BN_ 128
#define BK_ 32
#define STAGES_ 4
#define STG_BYTES_ 32768
#define OFF_AH 0
#define OFF_AL 8192
#define OFF_BH 16384
#define OFF_BL 24576
#define GEMM_SMEM (STAGES_*STG_BYTES_)   // 131072

__device__ __forceinline__ uint32_t smem_to_u32(const void* p) {
    uint32_t a;
    asm("{ .reg .u64 t; cvta.to.shared.u64 t, %1; cvt.u32.u64 %0, t; }"
        : "=r"(a) : "l"(p));
    return a;
}
__device__ __forceinline__ uint32_t swz64(uint32_t b) { return b ^ ((b >> 3) & 0x30); }

#define CP_ASYNC16(sa, ga) \
    asm volatile("cp.async.cg.shared.global [%0], [%1], 16;" :: "r"((uint32_t)(sa)), "l"(ga))
#define CP_COMMIT() asm volatile("cp.async.commit_group;" ::: "memory")
#define CP_WAIT2()  asm volatile("cp.async.wait_group 2;" ::: "memory")

#define LDSM4(r, addr) \
    asm volatile("ldmatrix.sync.aligned.m8n8.x4.shared.b16 {%0,%1,%2,%3}, [%4];" \
        : "=r"((r)[0]), "=r"((r)[1]), "=r"((r)[2]), "=r"((r)[3]) : "r"(addr))

#define MMA16816(c, a, b0, b1) \
    asm volatile("mma.sync.aligned.m16n8k16.row.col.f32.bf16.bf16.f32 " \
        "{%0,%1,%2,%3}, {%4,%5,%6,%7}, {%8,%9}, {%0,%1,%2,%3};" \
        : "+f"((c)[0]), "+f"((c)[1]), "+f"((c)[2]), "+f"((c)[3]) \
        : "r"((a)[0]), "r"((a)[1]), "r"((a)[2]), "r"((a)[3]), "r"(b0), "r"(b1))

// ---------------------------------------------------------------------------
// scratch
// ---------------------------------------------------------------------------
__device__ float g_qkv  [(size_t)M1_ * 3 * HID_];
__device__ __nv_bfloat16 g_xh[(size_t)M1_ * HID_];
__device__ __nv_bfloat16 g_xl[(size_t)M1_ * HID_];
__device__ __nv_bfloat16 g_ah[(size_t)M1_ * HID_];
__device__ __nv_bfloat16 g_al[(size_t)M1_ * HID_];
__device__ __nv_bfloat16 g_wqh[(size_t)3 * HID_ * HID_];
__device__ __nv_bfloat16 g_wql[(size_t)3 * HID_ * HID_];
__device__ __nv_bfloat16 g_woh[(size_t)HID_ * HID_];
__device__ __nv_bfloat16 g_wol[(size_t)HID_ * HID_];
__device__ float g_numloc[B_*NH_*S_];
__device__ float g_denloc[B_*NH_*S_];
__device__ float g_kvloc [B_*NH_*CH_*HD_];
__device__ float g_ksloc [B_*NH_*CH_*HD_];
__device__ float g_ckv   [B_*NH_*CH_*HD_];
__device__ float g_cks   [B_*NH_*CH_*HD_];

// ---------------------------------------------------------------------------
// conversions
// ---------------------------------------------------------------------------
__global__ void __launch_bounds__(256) split_fp32_bf16(
    const float* __restrict__ in, __nv_bfloat16* __restrict__ hi,
    __nv_bfloat16* __restrict__ lo, int n4)
{
    int i = blockIdx.x * blockDim.x + threadIdx.x;
    if (i >= n4) return;
    float4 v = ((const float4*)in)[i];
    __nv_bfloat16 h0 = __float2bfloat16(v.x), h1 = __float2bfloat16(v.y);
    __nv_bfloat16 h2 = __float2bfloat16(v.z), h3 = __float2bfloat16(v.w);
    __nv_bfloat16 l0 = __float2bfloat16(v.x - __bfloat162float(h0));
    __nv_bfloat16 l1 = __float2bfloat16(v.y - __bfloat162float(h1));
    __nv_bfloat16 l2 = __float2bfloat16(v.z - __bfloat162float(h2));
    __nv_bfloat16 l3 = __float2bfloat16(v.w - __bfloat162float(h3));
    __nv_bfloat162 ha, hb, la, lb;
    ha.x = h0; ha.y = h1; hb.x = h2; hb.y = h3;
    la.x = l0; la.y = l1; lb.x = l2; lb.y = l3;
    ((__nv_bfloat162*)hi)[2*i]   = ha;
    ((__nv_bfloat162*)hi)[2*i+1] = hb;
    ((__nv_bfloat162*)lo)[2*i]   = la;
    ((__nv_bfloat162*)lo)[2*i+1] = lb;
}

// W[K,N] fp32 -> T[N,K] bf16 hi/lo
__global__ void __launch_bounds__(256) trans_split(
    const float* __restrict__ W, __nv_bfloat16* __restrict__ Th,
    __nv_bfloat16* __restrict__ Tl, int K, int N)
{
    __shared__ float tile[32][33];
    int tx = threadIdx.x, ty = threadIdx.y;
    int bx = blockIdx.x * 32;  // N
    int by = blockIdx.y * 32;  // K
    #pragma unroll
    for (int j = 0; j < 4; j++)
        tile[ty + j*8][tx] = W[(size_t)(by + ty + j*8) * N + bx + tx];
    __syncthreads();
    #pragma unroll
    for (int j = 0; j < 4; j++) {
        float v = tile[tx][ty + j*8];
        __nv_bfloat16 h = __float2bfloat16(v);
        __nv_bfloat16 l = __float2bfloat16(v - __bfloat162float(h));
        size_t o = (size_t)(bx + ty + j*8) * K + by + tx;
        Th[o] = h; Tl[o] = l;
    }
}

// ---------------------------------------------------------------------------
// split-bf16 mma.sync GEMM:  C[M,N] = A[M,K] * B[N,K]^T
// ---------------------------------------------------------------------------
__device__ __forceinline__ void load_stage_g(
    uint32_t sb, int it, int m0, int n0, int K,
    const __nv_bfloat16* __restrict__ Ah, const __nv_bfloat16* __restrict__ Al,
    const __nv_bfloat16* __restrict__ Bh, const __nv_bfloat16* __restrict__ Bl,
    int tid)
{
    uint32_t stg = sb + (uint32_t)(it & (STAGES_ - 1)) * STG_BYTES_;
    const int k0 = it * BK_;
    #pragma unroll
    for (int h = 0; h < 2; h++) {
        int n = tid + h * 256;        // 0..511
        int row = n >> 2, ch = n & 3;
        uint32_t so = swz64((uint32_t)(row * 64 + ch * 16));
        const size_t gA = (size_t)(m0 + row) * K + k0 + ch * 8;
        const size_t gB = (size_t)(n0 + row) * K + k0 + ch * 8;
        CP_ASYNC16(stg + OFF_AH + so, Ah + gA);
        CP_ASYNC16(stg + OFF_AL + so, Al + gA);
        CP_ASYNC16(stg + OFF_BH + so, Bh + gB);
        CP_ASYNC16(stg + OFF_BL + so, Bl + gB);
    }
}

__global__ void __launch_bounds__(256, 1) gemm_mma(
    const __nv_bfloat16* __restrict__ Ah, const __nv_bfloat16* __restrict__ Al,
    const __nv_bfloat16* __restrict__ Bh, const __nv_bfloat16* __restrict__ Bl,
    float* __restrict__ C, int N, int K)
{
    extern __shared__ char smem[];
    uint32_t sb = smem_to_u32(smem);
    const int tid = threadIdx.x;
    const int lane = tid & 31;
    const int wid = tid >> 5;
    const int wm = wid & 1;
    const int wn = wid >> 1;

    const int m0 = blockIdx.y * BM_;
    const int n0 = blockIdx.x * BN_;
    const int nk = K / BK_;

    float acc[4][4][4];
    #pragma unroll
    for (int a = 0; a < 4; a++)
        #pragma unroll
        for (int b = 0; b < 4; b++)
            #pragma unroll
            for (int c = 0; c < 4; c++) acc[a][b][c] = 0.f;

    load_stage_g(sb, 0, m0, n0, K, Ah, Al, Bh, Bl, tid); CP_COMMIT();
    load_stage_g(sb, 1, m0, n0, K, Ah, Al, Bh, Bl, tid); CP_COMMIT();
    load_stage_g(sb, 2, m0, n0, K, Ah, Al, Bh, Bl, tid); CP_COMMIT();

    const int aRow = wm * 64 + (lane & 15);
    const int aKh  = lane >> 4;
    const int bRow = wn * 32 + (lane & 7) + ((lane >> 4) << 3);
    const int bKh  = (lane >> 3) & 1;

    for (int i = 0; i < nk; i++) {
        CP_WAIT2();
        __syncthreads();
        uint32_t stg = sb + (uint32_t)(i & (STAGES_ - 1)) * STG_BYTES_;

        #pragma unroll
        for (int ks = 0; ks < 2; ks++) {
            uint32_t ah[4][4], al[4][4], bh[2][4], bl[2][4];
            #pragma unroll
            for (int mt = 0; mt < 4; mt++) {
                uint32_t off = swz64((uint32_t)((aRow + mt * 16) * 64 + (ks * 2 + aKh) * 16));
                LDSM4(ah[mt], stg + OFF_AH + off);
                LDSM4(al[mt], stg + OFF_AL + off);
            }
            #pragma unroll
            for (int ng = 0; ng < 2; ng++) {
                uint32_t off = swz64((uint32_t)((bRow + ng * 16) * 64 + (ks * 2 + bKh) * 16));
                LDSM4(bh[ng], stg + OFF_BH + off);
                LDSM4(bl[ng], stg + OFF_BL + off);
            }
            // product-major order: 16 independent accumulators between
            // same-acc reuses (kills the HMMA RAW chain)
            #pragma unroll
            for (int mt = 0; mt < 4; mt++)
                #pragma unroll
                for (int nt = 0; nt < 4; nt++) {
                    const int ng = nt >> 1, p2 = (nt & 1) * 2;
                    MMA16816(acc[mt][nt], ah[mt], bh[ng][p2], bh[ng][p2 + 1]);
                }
            #pragma unroll
            for (int mt = 0; mt < 4; mt++)
                #pragma unroll
                for (int nt = 0; nt < 4; nt++) {
                    const int ng = nt >> 1, p2 = (nt & 1) * 2;
                    MMA16816(acc[mt][nt], ah[mt], bl[ng][p2], bl[ng][p2 + 1]);
                }
            #pragma unroll
            for (int mt = 0; mt < 4; mt++)
                #pragma unroll
                for (int nt = 0; nt < 4; nt++) {
                    const int ng = nt >> 1, p2 = (nt & 1) * 2;
                    MMA16816(acc[mt][nt], al[mt], bh[ng][p2], bh[ng][p2 + 1]);
                }
        }
        if (i + 3 < nk)
            load_stage_g(sb, i + 3, m0, n0, K, Ah, Al, Bh, Bl, tid);
        CP_COMMIT();
    }

    const int rb = m0 + wm * 64 + (lane >> 2);
    const int cb = n0 + wn * 32 + (lane & 3) * 2;
    #pragma unroll
    for (int mt = 0; mt < 4; mt++) {
        #pragma unroll
        for (int nt = 0; nt < 4; nt++) {
            float* p0 = C + (size_t)(rb + mt * 16) * N + cb + nt * 8;
            float* p1 = C + (size_t)(rb + mt * 16 + 8) * N + cb + nt * 8;
            *(float2*)p0 = make_float2(acc[mt][nt][0], acc[mt][nt][1]);
            *(float2*)p1 = make_float2(acc[mt][nt][2], acc[mt][nt][3]);
        }
    }
}

// ---------------------------------------------------------------------------
// scan — warp-per-(bh,chunk); lane owns 4 dims (float4); shfl-only reductions
// ---------------------------------------------------------------------------
__device__ __forceinline__ float phi_f(float u) { return u > 0.f ? u + 1.f : expf(u); }
__device__ __forceinline__ float sigmoid_f(float p) { return 1.f / (1.f + expf(-p)); }

__device__ __forceinline__ float2 warp_red2(float a, float b) {
    #pragma unroll
    for (int off = 16; off > 0; off >>= 1) {
        a += __shfl_xor_sync(0xffffffffu, a, off);
        b += __shfl_xor_sync(0xffffffffu, b, off);
    }
    return make_float2(a, b);
}

__global__ void __launch_bounds__(128) scan_phaseA(
    const float* __restrict__ qkv, const float* __restrict__ mask,
    const float* __restrict__ decay_p,
    float* __restrict__ num_loc, float* __restrict__ den_loc,
    float* __restrict__ kv_loc, float* __restrict__ ks_loc)
{
    const int gw = (blockIdx.x * blockDim.x + threadIdx.x) >> 5;  // 0..1023
    const int lane = threadIdx.x & 31;
    const int c  = gw % CH_;
    const int bh = gw / CH_;
    const int h  = bh % NH_;
    const int b  = bh / NH_;
    const float decay = sigmoid_f(decay_p[h]);

    float4 kv = make_float4(0,0,0,0), ks = make_float4(0,0,0,0);
    const size_t qbase = ((size_t)(b * S_ + c * LCH_)) * (3 * HID_) + h * HD_ + lane * 4;
    const float* mrow = mask + (size_t)b * S_ + c * LCH_;

    for (int t = 0; t < LCH_; t++) {
        size_t off = qbase + (size_t)t * (3 * HID_);
        float4 q4 = *(const float4*)(qkv + off);
        float4 k4 = *(const float4*)(qkv + off + HID_);
        float4 v4 = *(const float4*)(qkv + off + 2 * HID_);
        float m = mrow[t];
        float4 qp = make_float4(phi_f(q4.x), phi_f(q4.y), phi_f(q4.z), phi_f(q4.w));
        float4 kp = make_float4(phi_f(k4.x)*m, phi_f(k4.y)*m, phi_f(k4.z)*m, phi_f(k4.w)*m);
        kv.x = decay*kv.x + kp.x*v4.x*m; kv.y = decay*kv.y + kp.y*v4.y*m;
        kv.z = decay*kv.z + kp.z*v4.z*m; kv.w = decay*kv.w + kp.w*v4.w*m;
        ks.x = decay*ks.x + kp.x; ks.y = decay*ks.y + kp.y;
        ks.z = decay*ks.z + kp.z; ks.w = decay*ks.w + kp.w;
        float nl = qp.x*kv.x + qp.y*kv.y + qp.z*kv.z + qp.w*kv.w;
        float dl = qp.x*ks.x + qp.y*ks.y + qp.z*ks.z + qp.w*ks.w;
        float2 r = warp_red2(nl, dl);
        if (lane == 0) {
            int s = c * LCH_ + t;
            num_loc[(size_t)bh * S_ + s] = r.x;
            den_loc[(size_t)bh * S_ + s] = r.y;
        }
    }
    size_t sidx = ((size_t)bh * CH_ + c) * HD_ + lane * 4;
    *(float4*)(kv_loc + sidx) = kv;
    *(float4*)(ks_loc + sidx) = ks;
}

__global__ void __launch_bounds__(128) scan_phaseB(
    const float* __restrict__ kv0, const float* __restrict__ ks0,
    const float* __restrict__ decay_p,
    const float* __restrict__ kv_loc, const float* __restrict__ ks_loc,
    float* __restrict__ carry_kv, float* __restrict__ carry_ks,
    float* __restrict__ state_out, int write_states)
{
    const int bh = blockIdx.x;
    const int h  = bh % NH_;
    const int d  = threadIdx.x;
    const float decay = sigmoid_f(decay_p[h]);
    float dL = 1.f;
    #pragma unroll
    for (int i = 0; i < LCH_; i++) dL *= decay;
    float ckv = kv0[(size_t)bh * HD_ + d];
    float cks = ks0[(size_t)bh * HD_ + d];
    #pragma unroll
    for (int c = 0; c < CH_; c++) {
        size_t idx = ((size_t)bh * CH_ + c) * HD_ + d;
        carry_kv[idx] = ckv;
        carry_ks[idx] = cks;
        ckv = dL * ckv + kv_loc[idx];
        cks = dL * cks + ks_loc[idx];
    }
    if (write_states) {
        state_out[(size_t)bh * HD_ + d] = ckv;
        state_out[(size_t)(B_ * NH_ * HD_) + (size_t)bh * HD_ + d] = cks;
    }
}

// phase C: correction + output, fused with bf16 hi/lo split for GEMM2
__global__ void __launch_bounds__(128) scan_phaseC(
    const float* __restrict__ qkv, const float* __restrict__ decay_p,
    const float* __restrict__ num_loc, const float* __restrict__ den_loc,
    const float* __restrict__ carry_kv, const float* __restrict__ carry_ks,
    __nv_bfloat16* __restrict__ ah, __nv_bfloat16* __restrict__ al)
{
    const int gw = (blockIdx.x * blockDim.x + threadIdx.x) >> 5;
    const int lane = threadIdx.x & 31;
    const int c  = gw % CH_;
    const int bh = gw / CH_;
    const int h  = bh % NH_;
    const int b  = bh / NH_;
    const float decay = sigmoid_f(decay_p[h]);

    size_t sidx = ((size_t)bh * CH_ + c) * HD_ + lane * 4;
    const float4 ckv = *(const float4*)(carry_kv + sidx);
    const float4 cks = *(const float4*)(carry_ks + sidx);
    const size_t qbase = ((size_t)(b * S_ + c * LCH_)) * (3 * HID_) + h * HD_ + lane * 4;
    float dp = decay;

    for (int t = 0; t < LCH_; t++) {
        float4 q4 = *(const float4*)(qkv + qbase + (size_t)t * (3 * HID_));
        float4 qp = make_float4(phi_f(q4.x), phi_f(q4.y), phi_f(q4.z), phi_f(q4.w));
        float nl = qp.x*ckv.x + qp.y*ckv.y + qp.z*ckv.z + qp.w*ckv.w;
        float dl = qp.x*cks.x + qp.y*cks.y + qp.z*cks.z + qp.w*cks.w;
        float2 r = warp_red2(nl, dl);
        int s = c * LCH_ + t;
        float num = num_loc[(size_t)bh * S_ + s] + dp * r.x;
        float den = fmaxf(den_loc[(size_t)bh * S_ + s] + dp * r.y, 1e-6f);
        float sc = num / den;
        float4 o = make_float4(sc*qp.x, sc*qp.y, sc*qp.z, sc*qp.w);
        size_t oidx = ((size_t)(b * S_ + s)) * HID_ + h * HD_ + lane * 4;
        __nv_bfloat162 h01, h23, l01, l23;
        h01.x = __float2bfloat16(o.x); h01.y = __float2bfloat16(o.y);
        h23.x = __float2bfloat16(o.z); h23.y = __float2bfloat16(o.w);
        l01.x = __float2bfloat16(o.x - __bfloat162float(h01.x));
        l01.y = __float2bfloat16(o.y - __bfloat162float(h01.y));
        l23.x = __float2bfloat16(o.z - __bfloat162float(h23.x));
        l23.y = __float2bfloat16(o.w - __bfloat162float(h23.y));
        *(__nv_bfloat162*)(ah + oidx)     = h01;
        *(__nv_bfloat162*)(ah + oidx + 2) = h23;
        *(__nv_bfloat162*)(al + oidx)     = l01;
        *(__nv_bfloat162*)(al + oidx + 2) = l23;
        dp *= decay;
    }
}

// ---------------------------------------------------------------------------
// launch
// ---------------------------------------------------------------------------
extern "C" void kernel_launch(void* const* d_in, const int* in_sizes, int n_in,
                              void* d_out, int out_size)
{
    const float* x     = (const float*)d_in[0];
    const float* kv0   = (const float*)d_in[1];
    const float* ks0   = (const float*)d_in[2];
    const float* mask  = (const float*)d_in[3];
    const float* Wqkv  = (const float*)d_in[4];
    const float* Wout  = (const float*)d_in[5];
    const float* decay = (const float*)d_in[6];
    float* out = (float*)d_out;

    void* p;
    cudaGetSymbolAddress(&p, g_qkv);    float* qkvbuf = (float*)p;
    cudaGetSymbolAddress(&p, g_xh);     __nv_bfloat16* xh = (__nv_bfloat16*)p;
    cudaGetSymbolAddress(&p, g_xl);     __nv_bfloat16* xl = (__nv_bfloat16*)p;
    cudaGetSymbolAddress(&p, g_ah);     __nv_bfloat16* ah = (__nv_bfloat16*)p;
    cudaGetSymbolAddress(&p, g_al);     __nv_bfloat16* al = (__nv_bfloat16*)p;
    cudaGetSymbolAddress(&p, g_wqh);    __nv_bfloat16* wqh = (__nv_bfloat16*)p;
    cudaGetSymbolAddress(&p, g_wql);    __nv_bfloat16* wql = (__nv_bfloat16*)p;
    cudaGetSymbolAddress(&p, g_woh);    __nv_bfloat16* woh = (__nv_bfloat16*)p;
    cudaGetSymbolAddress(&p, g_wol);    __nv_bfloat16* wol = (__nv_bfloat16*)p;
    cudaGetSymbolAddress(&p, g_numloc); float* numloc = (float*)p;
    cudaGetSymbolAddress(&p, g_denloc); float* denloc = (float*)p;
    cudaGetSymbolAddress(&p, g_kvloc);  float* kvloc = (float*)p;
    cudaGetSymbolAddress(&p, g_ksloc);  float* ksloc = (float*)p;
    cudaGetSymbolAddress(&p, g_ckv);    float* ckv = (float*)p;
    cudaGetSymbolAddress(&p, g_cks);    float* cks = (float*)p;

    cudaFuncSetAttribute(gemm_mma, cudaFuncAttributeMaxDynamicSharedMemorySize, GEMM_SMEM);

    const size_t out_main = (size_t)M1_ * HID_;
    const int write_states = (out_size >= (int)(out_main + 2 * B_ * NH_ * HD_));
    float* state_out = out + out_main;

    // 1) precision splits + weight transposes
    {
        int n4 = (M1_ * HID_) / 4;
        split_fp32_bf16<<<(n4 + 255) / 256, 256>>>(x, xh, xl, n4);
    }
    {
        dim3 blk(32, 8);
        dim3 g1(3 * HID_ / 32, HID_ / 32);
        trans_split<<<g1, blk>>>(Wqkv, wqh, wql, HID_, 3 * HID_);
        dim3 g2(HID_ / 32, HID_ / 32);
        trans_split<<<g2, blk>>>(Wout, woh, wol, HID_, HID_);
    }

    // 2) qkv = x @ W_qkv
    {
        dim3 grid(3 * HID_ / BN_, M1_ / BM_);
        gemm_mma<<<grid, 256, GEMM_SMEM>>>(xh, xl, wqh, wql, qkvbuf, 3 * HID_, HID_);
    }

    // 3) scan (warp-level; phase C fuses the bf16 split)
    scan_phaseA<<<(B_ * NH_ * CH_) / 4, 128>>>(qkvbuf, mask, decay, numloc, denloc, kvloc, ksloc);
    scan_phaseB<<<B_ * NH_, HD_>>>(kv0, ks0, decay, kvloc, ksloc, ckv, cks,
                                   state_out, write_states);
    scan_phaseC<<<(B_ * NH_ * CH_) / 4, 128>>>(qkvbuf, decay, numloc, denloc, ckv, cks, ah, al);

    // 4) out = attn @ W_out
    {
        dim3 grid(HID_ / BN_, M1_ / BM_);
        gemm_mma<<<grid, 256, GEMM_SMEM>>>(ah, al, woh, wol, out, HID_, HID_);
    }
}

// round 5
// speedup vs baseline: 1.0716x; 1.0716x over previous
#include <cuda_runtime.h>
#include <cuda_bf16.h>
#include <math.h>
#include <stdint.h>

// Problem constants
#define B_   4
#define S_   2048
#define HID_ 2048
#define NH_  16
#define HD_  128
#define CH_  32
#define LCH_ 64
#define M1_  (B_*S_)   // 8192

// GEMM tiling (warp-level mma.sync)
#define BM_ 128
#define BN_ 128
#define BK_ 32
#define STAGES_ 3
#define STG_BYTES_ 32768
#define OFF_AH 0
#define OFF_AL 8192
#define OFF_BH 16384
#define OFF_BL 24576
#define GEMM_SMEM (STAGES_*STG_BYTES_)   // 98304 -> 2 CTAs/SM

__device__ __forceinline__ uint32_t smem_to_u32(const void* p) {
    uint32_t a;
    asm("{ .reg .u64 t; cvta.to.shared.u64 t, %1; cvt.u32.u64 %0, t; }"
        : "=r"(a) : "l"(p));
    return a;
}
__device__ __forceinline__ uint32_t swz64(uint32_t b) { return b ^ ((b >> 3) & 0x30); }

#define CP_ASYNC16(sa, ga) \
    asm volatile("cp.async.cg.shared.global [%0], [%1], 16;" :: "r"((uint32_t)(sa)), "l"(ga))
#define CP_COMMIT() asm volatile("cp.async.commit_group;" ::: "memory")
#define CP_WAIT1()  asm volatile("cp.async.wait_group 1;" ::: "memory")

#define LDSM4(r, addr) \
    asm volatile("ldmatrix.sync.aligned.m8n8.x4.shared.b16 {%0,%1,%2,%3}, [%4];" \
        : "=r"((r)[0]), "=r"((r)[1]), "=r"((r)[2]), "=r"((r)[3]) : "r"(addr))

#define MMA16816(c, a, b0, b1) \
    asm volatile("mma.sync.aligned.m16n8k16.row.col.f32.bf16.bf16.f32 " \
        "{%0,%1,%2,%3}, {%4,%5,%6,%7}, {%8,%9}, {%0,%1,%2,%3};" \
        : "+f"((c)[0]), "+f"((c)[1]), "+f"((c)[2]), "+f"((c)[3]) \
        : "r"((a)[0]), "r"((a)[1]), "r"((a)[2]), "r"((a)[3]), "r"(b0), "r"(b1))

// ---------------------------------------------------------------------------
// scratch
// ---------------------------------------------------------------------------
__device__ float g_qkv  [(size_t)M1_ * 3 * HID_];
__device__ __nv_bfloat16 g_xh[(size_t)M1_ * HID_];
__device__ __nv_bfloat16 g_xl[(size_t)M1_ * HID_];
__device__ __nv_bfloat16 g_ah[(size_t)M1_ * HID_];
__device__ __nv_bfloat16 g_al[(size_t)M1_ * HID_];
__device__ __nv_bfloat16 g_wqh[(size_t)3 * HID_ * HID_];
__device__ __nv_bfloat16 g_wql[(size_t)3 * HID_ * HID_];
__device__ __nv_bfloat16 g_woh[(size_t)HID_ * HID_];
__device__ __nv_bfloat16 g_wol[(size_t)HID_ * HID_];
__device__ float g_numloc[B_*NH_*S_];
__device__ float g_denloc[B_*NH_*S_];
__device__ float g_kvloc [B_*NH_*CH_*HD_];
__device__ float g_ksloc [B_*NH_*CH_*HD_];
__device__ float g_ckv   [B_*NH_*CH_*HD_];
__device__ float g_cks   [B_*NH_*CH_*HD_];

// ---------------------------------------------------------------------------
// conversions
// ---------------------------------------------------------------------------
__global__ void __launch_bounds__(256) split_fp32_bf16(
    const float* __restrict__ in, __nv_bfloat16* __restrict__ hi,
    __nv_bfloat16* __restrict__ lo, int n4)
{
    int i = blockIdx.x * blockDim.x + threadIdx.x;
    if (i >= n4) return;
    float4 v = ((const float4*)in)[i];
    __nv_bfloat16 h0 = __float2bfloat16(v.x), h1 = __float2bfloat16(v.y);
    __nv_bfloat16 h2 = __float2bfloat16(v.z), h3 = __float2bfloat16(v.w);
    __nv_bfloat16 l0 = __float2bfloat16(v.x - __bfloat162float(h0));
    __nv_bfloat16 l1 = __float2bfloat16(v.y - __bfloat162float(h1));
    __nv_bfloat16 l2 = __float2bfloat16(v.z - __bfloat162float(h2));
    __nv_bfloat16 l3 = __float2bfloat16(v.w - __bfloat162float(h3));
    __nv_bfloat162 ha, hb, la, lb;
    ha.x = h0; ha.y = h1; hb.x = h2; hb.y = h3;
    la.x = l0; la.y = l1; lb.x = l2; lb.y = l3;
    ((__nv_bfloat162*)hi)[2*i]   = ha;
    ((__nv_bfloat162*)hi)[2*i+1] = hb;
    ((__nv_bfloat162*)lo)[2*i]   = la;
    ((__nv_bfloat162*)lo)[2*i+1] = lb;
}

// W[K,N] fp32 -> T[N,K] bf16 hi/lo
__global__ void __launch_bounds__(256) trans_split(
    const float* __restrict__ W, __nv_bfloat16* __restrict__ Th,
    __nv_bfloat16* __restrict__ Tl, int K, int N)
{
    __shared__ float tile[32][33];
    int tx = threadIdx.x, ty = threadIdx.y;
    int bx = blockIdx.x * 32;  // N
    int by = blockIdx.y * 32;  // K
    #pragma unroll
    for (int j = 0; j < 4; j++)
        tile[ty + j*8][tx] = W[(size_t)(by + ty + j*8) * N + bx + tx];
    __syncthreads();
    #pragma unroll
    for (int j = 0; j < 4; j++) {
        float v = tile[tx][ty + j*8];
        __nv_bfloat16 h = __float2bfloat16(v);
        __nv_bfloat16 l = __float2bfloat16(v - __bfloat162float(h));
        size_t o = (size_t)(bx + ty + j*8) * K + by + tx;
        Th[o] = h; Tl[o] = l;
    }
}

// ---------------------------------------------------------------------------
// split-bf16 mma.sync GEMM:  C[M,N] = A[M,K] * B[N,K]^T
// 3-stage cp.async pipeline, 2 CTAs/SM (<=128 regs), 256 threads (8 warps 2x4)
// ---------------------------------------------------------------------------
__device__ __forceinline__ void load_stage_g(
    uint32_t sb, int it, int m0, int n0, int K,
    const __nv_bfloat16* __restrict__ Ah, const __nv_bfloat16* __restrict__ Al,
    const __nv_bfloat16* __restrict__ Bh, const __nv_bfloat16* __restrict__ Bl,
    int tid)
{
    uint32_t stg = sb + (uint32_t)(it % STAGES_) * STG_BYTES_;
    const int k0 = it * BK_;
    #pragma unroll
    for (int h = 0; h < 2; h++) {
        int n = tid + h * 256;        // 0..511
        int row = n >> 2, ch = n & 3;
        uint32_t so = swz64((uint32_t)(row * 64 + ch * 16));
        const size_t gA = (size_t)(m0 + row) * K + k0 + ch * 8;
        const size_t gB = (size_t)(n0 + row) * K + k0 + ch * 8;
        CP_ASYNC16(stg + OFF_AH + so, Ah + gA);
        CP_ASYNC16(stg + OFF_AL + so, Al + gA);
        CP_ASYNC16(stg + OFF_BH + so, Bh + gB);
        CP_ASYNC16(stg + OFF_BL + so, Bl + gB);
    }
}

__global__ void __launch_bounds__(256, 2) gemm_mma(
    const __nv_bfloat16* __restrict__ Ah, const __nv_bfloat16* __restrict__ Al,
    const __nv_bfloat16* __restrict__ Bh, const __nv_bfloat16* __restrict__ Bl,
    float* __restrict__ C, int N, int K)
{
    extern __shared__ char smem[];
    uint32_t sb = smem_to_u32(smem);
    const int tid = threadIdx.x;
    const int lane = tid & 31;
    const int wid = tid >> 5;
    const int wm = wid & 1;
    const int wn = wid >> 1;

    const int m0 = blockIdx.y * BM_;
    const int n0 = blockIdx.x * BN_;
    const int nk = K / BK_;

    float acc[4][4][4];
    #pragma unroll
    for (int a = 0; a < 4; a++)
        #pragma unroll
        for (int b = 0; b < 4; b++)
            #pragma unroll
            for (int c = 0; c < 4; c++) acc[a][b][c] = 0.f;

    load_stage_g(sb, 0, m0, n0, K, Ah, Al, Bh, Bl, tid); CP_COMMIT();
    load_stage_g(sb, 1, m0, n0, K, Ah, Al, Bh, Bl, tid); CP_COMMIT();

    const int aRow = wm * 64 + (lane & 15);
    const int aKh  = lane >> 4;
    const int bRow = wn * 32 + (lane & 7) + ((lane >> 4) << 3);
    const int bKh  = (lane >> 3) & 1;

    for (int i = 0; i < nk; i++) {
        CP_WAIT1();
        __syncthreads();
        uint32_t stg = sb + (uint32_t)(i % STAGES_) * STG_BYTES_;

        #pragma unroll
        for (int ks = 0; ks < 2; ks++) {
            uint32_t ah[4][4], al[4][4], bh[2][4], bl[2][4];
            #pragma unroll
            for (int mt = 0; mt < 4; mt++) {
                uint32_t off = swz64((uint32_t)((aRow + mt * 16) * 64 + (ks * 2 + aKh) * 16));
                LDSM4(ah[mt], stg + OFF_AH + off);
                LDSM4(al[mt], stg + OFF_AL + off);
            }
            #pragma unroll
            for (int ng = 0; ng < 2; ng++) {
                uint32_t off = swz64((uint32_t)((bRow + ng * 16) * 64 + (ks * 2 + bKh) * 16));
                LDSM4(bh[ng], stg + OFF_BH + off);
                LDSM4(bl[ng], stg + OFF_BL + off);
            }
            #pragma unroll
            for (int mt = 0; mt < 4; mt++)
                #pragma unroll
                for (int nt = 0; nt < 4; nt++) {
                    const int ng = nt >> 1, p2 = (nt & 1) * 2;
                    MMA16816(acc[mt][nt], ah[mt], bh[ng][p2], bh[ng][p2 + 1]);
                }
            #pragma unroll
            for (int mt = 0; mt < 4; mt++)
                #pragma unroll
                for (int nt = 0; nt < 4; nt++) {
                    const int ng = nt >> 1, p2 = (nt & 1) * 2;
                    MMA16816(acc[mt][nt], ah[mt], bl[ng][p2], bl[ng][p2 + 1]);
                }
            #pragma unroll
            for (int mt = 0; mt < 4; mt++)
                #pragma unroll
                for (int nt = 0; nt < 4; nt++) {
                    const int ng = nt >> 1, p2 = (nt & 1) * 2;
                    MMA16816(acc[mt][nt], al[mt], bh[ng][p2], bh[ng][p2 + 1]);
                }
        }
        if (i + 2 < nk)
            load_stage_g(sb, i + 2, m0, n0, K, Ah, Al, Bh, Bl, tid);
        CP_COMMIT();
    }

    const int rb = m0 + wm * 64 + (lane >> 2);
    const int cb = n0 + wn * 32 + (lane & 3) * 2;
    #pragma unroll
    for (int mt = 0; mt < 4; mt++) {
        #pragma unroll
        for (int nt = 0; nt < 4; nt++) {
            float* p0 = C + (size_t)(rb + mt * 16) * N + cb + nt * 8;
            float* p1 = C + (size_t)(rb + mt * 16 + 8) * N + cb + nt * 8;
            *(float2*)p0 = make_float2(acc[mt][nt][0], acc[mt][nt][1]);
            *(float2*)p1 = make_float2(acc[mt][nt][2], acc[mt][nt][3]);
        }
    }
}

// ---------------------------------------------------------------------------
// scan — warp-per-(bh,chunk); CH=32 doubles parallelism vs round 4
// ---------------------------------------------------------------------------
__device__ __forceinline__ float phi_f(float u) { return u > 0.f ? u + 1.f : expf(u); }
__device__ __forceinline__ float sigmoid_f(float p) { return 1.f / (1.f + expf(-p)); }

__device__ __forceinline__ float2 warp_red2(float a, float b) {
    #pragma unroll
    for (int off = 16; off > 0; off >>= 1) {
        a += __shfl_xor_sync(0xffffffffu, a, off);
        b += __shfl_xor_sync(0xffffffffu, b, off);
    }
    return make_float2(a, b);
}

__global__ void __launch_bounds__(128) scan_phaseA(
    const float* __restrict__ qkv, const float* __restrict__ mask,
    const float* __restrict__ decay_p,
    float* __restrict__ num_loc, float* __restrict__ den_loc,
    float* __restrict__ kv_loc, float* __restrict__ ks_loc)
{
    const int gw = (blockIdx.x * blockDim.x + threadIdx.x) >> 5;  // 0..2047
    const int lane = threadIdx.x & 31;
    const int c  = gw % CH_;
    const int bh = gw / CH_;
    const int h  = bh % NH_;
    const int b  = bh / NH_;
    const float decay = sigmoid_f(decay_p[h]);

    float4 kv = make_float4(0,0,0,0), ks = make_float4(0,0,0,0);
    const size_t qbase = ((size_t)(b * S_ + c * LCH_)) * (3 * HID_) + h * HD_ + lane * 4;
    const float* mrow = mask + (size_t)b * S_ + c * LCH_;

    for (int t = 0; t < LCH_; t++) {
        size_t off = qbase + (size_t)t * (3 * HID_);
        float4 q4 = *(const float4*)(qkv + off);
        float4 k4 = *(const float4*)(qkv + off + HID_);
        float4 v4 = *(const float4*)(qkv + off + 2 * HID_);
        float m = mrow[t];
        float4 qp = make_float4(phi_f(q4.x), phi_f(q4.y), phi_f(q4.z), phi_f(q4.w));
        float4 kp = make_float4(phi_f(k4.x)*m, phi_f(k4.y)*m, phi_f(k4.z)*m, phi_f(k4.w)*m);
        kv.x = decay*kv.x + kp.x*v4.x*m; kv.y = decay*kv.y + kp.y*v4.y*m;
        kv.z = decay*kv.z + kp.z*v4.z*m; kv.w = decay*kv.w + kp.w*v4.w*m;
        ks.x = decay*ks.x + kp.x; ks.y = decay*ks.y + kp.y;
        ks.z = decay*ks.z + kp.z; ks.w = decay*ks.w + kp.w;
        float nl = qp.x*kv.x + qp.y*kv.y + qp.z*kv.z + qp.w*kv.w;
        float dl = qp.x*ks.x + qp.y*ks.y + qp.z*ks.z + qp.w*ks.w;
        float2 r = warp_red2(nl, dl);
        if (lane == 0) {
            int s = c * LCH_ + t;
            num_loc[(size_t)bh * S_ + s] = r.x;
            den_loc[(size_t)bh * S_ + s] = r.y;
        }
    }
    size_t sidx = ((size_t)bh * CH_ + c) * HD_ + lane * 4;
    *(float4*)(kv_loc + sidx) = kv;
    *(float4*)(ks_loc + sidx) = ks;
}

__global__ void __launch_bounds__(128) scan_phaseB(
    const float* __restrict__ kv0, const float* __restrict__ ks0,
    const float* __restrict__ decay_p,
    const float* __restrict__ kv_loc, const float* __restrict__ ks_loc,
    float* __restrict__ carry_kv, float* __restrict__ carry_ks,
    float* __restrict__ state_out, int write_states)
{
    const int bh = blockIdx.x;
    const int h  = bh % NH_;
    const int d  = threadIdx.x;
    const float decay = sigmoid_f(decay_p[h]);
    float dL = 1.f;
    #pragma unroll
    for (int i = 0; i < LCH_; i++) dL *= decay;
    float ckv = kv0[(size_t)bh * HD_ + d];
    float cks = ks0[(size_t)bh * HD_ + d];
    #pragma unroll
    for (int c = 0; c < CH_; c++) {
        size_t idx = ((size_t)bh * CH_ + c) * HD_ + d;
        carry_kv[idx] = ckv;
        carry_ks[idx] = cks;
        ckv = dL * ckv + kv_loc[idx];
        cks = dL * cks + ks_loc[idx];
    }
    if (write_states) {
        state_out[(size_t)bh * HD_ + d] = ckv;
        state_out[(size_t)(B_ * NH_ * HD_) + (size_t)bh * HD_ + d] = cks;
    }
}

// phase C: correction + output, fused with bf16 hi/lo split for GEMM2
__global__ void __launch_bounds__(128) scan_phaseC(
    const float* __restrict__ qkv, const float* __restrict__ decay_p,
    const float* __restrict__ num_loc, const float* __restrict__ den_loc,
    const float* __restrict__ carry_kv, const float* __restrict__ carry_ks,
    __nv_bfloat16* __restrict__ ah, __nv_bfloat16* __restrict__ al)
{
    const int gw = (blockIdx.x * blockDim.x + threadIdx.x) >> 5;
    const int lane = threadIdx.x & 31;
    const int c  = gw % CH_;
    const int bh = gw / CH_;
    const int h  = bh % NH_;
    const int b  = bh / NH_;
    const float decay = sigmoid_f(decay_p[h]);

    size_t sidx = ((size_t)bh * CH_ + c) * HD_ + lane * 4;
    const float4 ckv = *(const float4*)(carry_kv + sidx);
    const float4 cks = *(const float4*)(carry_ks + sidx);
    const size_t qbase = ((size_t)(b * S_ + c * LCH_)) * (3 * HID_) + h * HD_ + lane * 4;
    float dp = decay;

    for (int t = 0; t < LCH_; t++) {
        float4 q4 = *(const float4*)(qkv + qbase + (size_t)t * (3 * HID_));
        float4 qp = make_float4(phi_f(q4.x), phi_f(q4.y), phi_f(q4.z), phi_f(q4.w));
        float nl = qp.x*ckv.x + qp.y*ckv.y + qp.z*ckv.z + qp.w*ckv.w;
        float dl = qp.x*cks.x + qp.y*cks.y + qp.z*cks.z + qp.w*cks.w;
        float2 r = warp_red2(nl, dl);
        int s = c * LCH_ + t;
        float num = num_loc[(size_t)bh * S_ + s] + dp * r.x;
        float den = fmaxf(den_loc[(size_t)bh * S_ + s] + dp * r.y, 1e-6f);
        float sc = num / den;
        float4 o = make_float4(sc*qp.x, sc*qp.y, sc*qp.z, sc*qp.w);
        size_t oidx = ((size_t)(b * S_ + s)) * HID_ + h * HD_ + lane * 4;
        __nv_bfloat162 h01, h23, l01, l23;
        h01.x = __float2bfloat16(o.x); h01.y = __float2bfloat16(o.y);
        h23.x = __float2bfloat16(o.z); h23.y = __float2bfloat16(o.w);
        l01.x = __float2bfloat16(o.x - __bfloat162float(h01.x));
        l01.y = __float2bfloat16(o.y - __bfloat162float(h01.y));
        l23.x = __float2bfloat16(o.z - __bfloat162float(h23.x));
        l23.y = __float2bfloat16(o.w - __bfloat162float(h23.y));
        *(__nv_bfloat162*)(ah + oidx)     = h01;
        *(__nv_bfloat162*)(ah + oidx + 2) = h23;
        *(__nv_bfloat162*)(al + oidx)     = l01;
        *(__nv_bfloat162*)(al + oidx + 2) = l23;
        dp *= decay;
    }
}

// ---------------------------------------------------------------------------
// launch
// ---------------------------------------------------------------------------
extern "C" void kernel_launch(void* const* d_in, const int* in_sizes, int n_in,
                              void* d_out, int out_size)
{
    const float* x     = (const float*)d_in[0];
    const float* kv0   = (const float*)d_in[1];
    const float* ks0   = (const float*)d_in[2];
    const float* mask  = (const float*)d_in[3];
    const float* Wqkv  = (const float*)d_in[4];
    const float* Wout  = (const float*)d_in[5];
    const float* decay = (const float*)d_in[6];
    float* out = (float*)d_out;

    void* p;
    cudaGetSymbolAddress(&p, g_qkv);    float* qkvbuf = (float*)p;
    cudaGetSymbolAddress(&p, g_xh);     __nv_bfloat16* xh = (__nv_bfloat16*)p;
    cudaGetSymbolAddress(&p, g_xl);     __nv_bfloat16* xl = (__nv_bfloat16*)p;
    cudaGetSymbolAddress(&p, g_ah);     __nv_bfloat16* ah = (__nv_bfloat16*)p;
    cudaGetSymbolAddress(&p, g_al);     __nv_bfloat16* al = (__nv_bfloat16*)p;
    cudaGetSymbolAddress(&p, g_wqh);    __nv_bfloat16* wqh = (__nv_bfloat16*)p;
    cudaGetSymbolAddress(&p, g_wql);    __nv_bfloat16* wql = (__nv_bfloat16*)p;
    cudaGetSymbolAddress(&p, g_woh);    __nv_bfloat16* woh = (__nv_bfloat16*)p;
    cudaGetSymbolAddress(&p, g_wol);    __nv_bfloat16* wol = (__nv_bfloat16*)p;
    cudaGetSymbolAddress(&p, g_numloc); float* numloc = (float*)p;
    cudaGetSymbolAddress(&p, g_denloc); float* denloc = (float*)p;
    cudaGetSymbolAddress(&p, g_kvloc);  float* kvloc = (float*)p;
    cudaGetSymbolAddress(&p, g_ksloc);  float* ksloc = (float*)p;
    cudaGetSymbolAddress(&p, g_ckv);    float* ckv = (float*)p;
    cudaGetSymbolAddress(&p, g_cks);    float* cks = (float*)p;

    cudaFuncSetAttribute(gemm_mma, cudaFuncAttributeMaxDynamicSharedMemorySize, GEMM_SMEM);

    const size_t out_main = (size_t)M1_ * HID_;
    const int write_states = (out_size >= (int)(out_main + 2 * B_ * NH_ * HD_));
    float* state_out = out + out_main;

    // 1) precision splits + weight transposes
    {
        int n4 = (M1_ * HID_) / 4;
        split_fp32_bf16<<<(n4 + 255) / 256, 256>>>(x, xh, xl, n4);
    }
    {
        dim3 blk(32, 8);
        dim3 g1(3 * HID_ / 32, HID_ / 32);
        trans_split<<<g1, blk>>>(Wqkv, wqh, wql, HID_, 3 * HID_);
        dim3 g2(HID_ / 32, HID_ / 32);
        trans_split<<<g2, blk>>>(Wout, woh, wol, HID_, HID_);
    }

    // 2) qkv = x @ W_qkv
    {
        dim3 grid(3 * HID_ / BN_, M1_ / BM_);
        gemm_mma<<<grid, 256, GEMM_SMEM>>>(xh, xl, wqh, wql, qkvbuf, 3 * HID_, HID_);
    }

    // 3) scan
    scan_phaseA<<<(B_ * NH_ * CH_) / 4, 128>>>(qkvbuf, mask, decay, numloc, denloc, kvloc, ksloc);
    scan_phaseB<<<B_ * NH_, HD_>>>(kv0, ks0, decay, kvloc, ksloc, ckv, cks,
                                   state_out, write_states);
    scan_phaseC<<<(B_ * NH_ * CH_) / 4, 128>>>(qkvbuf, decay, numloc, denloc, ckv, cks, ah, al);

    // 4) out = attn @ W_out
    {
        dim3 grid(HID_ / BN_, M1_ / BM_);
        gemm_mma<<<grid, 256, GEMM_SMEM>>>(ah, al, woh, wol, out, HID_, HID_);
    }
}